// round 1
// baseline (speedup 1.0000x reference)
#include <cuda_runtime.h>
#include <cuda_bf16.h>

#define T_STEPS 2048
#define IN_DIM  118
#define EMB     128
#define H       1536
#define H4      6144
#define H2      1024
#define OUTD    128
#define CA      1792   // packed layer-0 row: 246 (ih) + 1536 (hh) + 10 pad
#define CB      3072   // packed layer-1 row: 1536 + 1536
#define NBLK    128
#define NTHR    512

// ---------------- device-global scratch (sanctioned workaround for no-alloc rule) ----
__device__ __align__(128) __nv_bfloat16 g_WA[(size_t)H4 * CA];   // ~21 MB
__device__ __align__(128) __nv_bfloat16 g_WB[(size_t)H4 * CB];   // ~37.7 MB
__device__ __align__(128) __nv_bfloat16 g_WC[(size_t)H2 * H];    // ~3.1 MB
__device__ __align__(128) __nv_bfloat16 g_WO[OUTD * H2];
__device__ __align__(128) __nv_bfloat16 g_WM[EMB * OUTD];
__device__ float g_h0v[H];
__device__ float g_h1v[H];
__device__ float g_zv[H2];
__device__ float g_embv[EMB];
__device__ unsigned g_count = 0;   // monotonic barrier counter (reset at launch end)
__device__ unsigned g_done  = 0;

// ---------------- weight pack/convert kernels ----------------------------------------
__global__ void pack_A(const float* __restrict__ Wih0, const float* __restrict__ Whh0) {
    size_t n = (size_t)H4 * CA;
    size_t stride = (size_t)gridDim.x * blockDim.x;
    for (size_t i = (size_t)blockIdx.x * blockDim.x + threadIdx.x; i < n; i += stride) {
        size_t r = i / CA;
        int c = (int)(i % CA);
        float v = 0.f;
        if (c < IN_DIM + EMB)            v = Wih0[r * (IN_DIM + EMB) + c];
        else if (c < IN_DIM + EMB + H)   v = Whh0[r * H + (c - IN_DIM - EMB)];
        g_WA[i] = __float2bfloat16(v);
    }
}

__global__ void pack_B(const float* __restrict__ Wih1, const float* __restrict__ Whh1) {
    size_t n = (size_t)H4 * CB;
    size_t stride = (size_t)gridDim.x * blockDim.x;
    for (size_t i = (size_t)blockIdx.x * blockDim.x + threadIdx.x; i < n; i += stride) {
        size_t r = i / CB;
        int c = (int)(i % CB);
        float v = (c < H) ? Wih1[r * H + c] : Whh1[r * H + (c - H)];
        g_WB[i] = __float2bfloat16(v);
    }
}

__global__ void pack_small(const float* __restrict__ Whl, const float* __restrict__ Wout,
                           const float* __restrict__ Wmap) {
    const size_t nC = (size_t)H2 * H, nO = (size_t)OUTD * H2, nM = (size_t)EMB * OUTD;
    size_t stride = (size_t)gridDim.x * blockDim.x;
    for (size_t i = (size_t)blockIdx.x * blockDim.x + threadIdx.x; i < nC + nO + nM; i += stride) {
        if (i < nC)            g_WC[i] = __float2bfloat16(Whl[i]);
        else if (i < nC + nO)  g_WO[i - nC] = __float2bfloat16(Wout[i - nC]);
        else                   g_WM[i - nC - nO] = __float2bfloat16(Wmap[i - nC - nO]);
    }
}

// ---------------- helpers -------------------------------------------------------------
__device__ __forceinline__ float wred(float a) {
    a += __shfl_xor_sync(0xffffffffu, a, 16);
    a += __shfl_xor_sync(0xffffffffu, a, 8);
    a += __shfl_xor_sync(0xffffffffu, a, 4);
    a += __shfl_xor_sync(0xffffffffu, a, 2);
    a += __shfl_xor_sync(0xffffffffu, a, 1);
    return a;
}

__device__ __forceinline__ float sigmoidf_(float x) { return 1.f / (1.f + expf(-x)); }

// Software grid barrier: monotonic counter, target = epoch*NBLK.
__device__ __forceinline__ void grid_sync(unsigned target) {
    __syncthreads();
    if (threadIdx.x == 0) {
        __threadfence();                       // release this block's writes to L2
        atomicAdd(&g_count, 1u);
        while (*(volatile unsigned*)&g_count < target) { }
        __threadfence();                       // acquire
    }
    __syncthreads();
}

// 8 bf16 * 8 f32 FMA into ACC; uses k, x0, x1 from enclosing scope.
#define FMA8(W, ACC) do {                                                                 \
    uint4 wv_ = *reinterpret_cast<const uint4*>((W) + k);                                 \
    float2 p0_ = __bfloat1622float2(*reinterpret_cast<const __nv_bfloat162*>(&wv_.x));    \
    float2 p1_ = __bfloat1622float2(*reinterpret_cast<const __nv_bfloat162*>(&wv_.y));    \
    float2 p2_ = __bfloat1622float2(*reinterpret_cast<const __nv_bfloat162*>(&wv_.z));    \
    float2 p3_ = __bfloat1622float2(*reinterpret_cast<const __nv_bfloat162*>(&wv_.w));    \
    ACC = fmaf(x0.x, p0_.x, ACC); ACC = fmaf(x0.y, p0_.y, ACC);                           \
    ACC = fmaf(x0.z, p1_.x, ACC); ACC = fmaf(x0.w, p1_.y, ACC);                           \
    ACC = fmaf(x1.x, p2_.x, ACC); ACC = fmaf(x1.y, p2_.y, ACC);                           \
    ACC = fmaf(x1.z, p3_.x, ACC); ACC = fmaf(x1.w, p3_.y, ACC);                           \
} while (0)

// 4 gate-row dot products sharing the SMEM x loads (warp covers 256 elems/iter).
template <int ITERS>
__device__ __forceinline__ void dot4(const __nv_bfloat16* __restrict__ w0,
                                     const __nv_bfloat16* __restrict__ w1,
                                     const __nv_bfloat16* __restrict__ w2,
                                     const __nv_bfloat16* __restrict__ w3,
                                     const float* __restrict__ sx, int lane,
                                     float& A0, float& A1, float& A2, float& A3) {
    A0 = A1 = A2 = A3 = 0.f;
    #pragma unroll 4
    for (int it = 0; it < ITERS; ++it) {
        const int k = it * 256 + lane * 8;
        float4 x0 = *reinterpret_cast<const float4*>(sx + k);
        float4 x1 = *reinterpret_cast<const float4*>(sx + k + 4);
        FMA8(w0, A0);
        FMA8(w1, A1);
        FMA8(w2, A2);
        FMA8(w3, A3);
    }
}

template <int ITERS>
__device__ __forceinline__ float dot1(const __nv_bfloat16* __restrict__ w0,
                                      const float* __restrict__ sx, int lane) {
    float A0 = 0.f;
    #pragma unroll 4
    for (int it = 0; it < ITERS; ++it) {
        const int k = it * 256 + lane * 8;
        float4 x0 = *reinterpret_cast<const float4*>(sx + k);
        float4 x1 = *reinterpret_cast<const float4*>(sx + k + 4);
        FMA8(w0, A0);
    }
    return A0;
}

// ---------------- persistent main kernel ----------------------------------------------
__global__ void __launch_bounds__(NTHR, 1) lstm_main(
    const float* __restrict__ inputVecs,
    const float* __restrict__ h0in, const float* __restrict__ c0in,
    const float* __restrict__ bi0, const float* __restrict__ bh0,
    const float* __restrict__ bi1, const float* __restrict__ bh1,
    const float* __restrict__ bhl, const float* __restrict__ bo,
    const float* __restrict__ bm,
    float* __restrict__ out) {
    __shared__ __align__(16) float sx[CB];   // 12 KB staging vector
    __shared__ float sy[OUTD];

    const int tid = threadIdx.x, lane = tid & 31, wid = tid >> 5, bid = blockIdx.x;
    const int j  = bid * 12 + wid;   // A/B unit (valid when wid<12): j in [0,1536)
    const int rC = bid * 8 + wid;    // C row   (valid when wid<8):  r in [0,1024)

    // init recurrent state in L2 + cell state in registers (fixed ownership)
    if (bid == 0) {
        for (int i = tid; i < H; i += NTHR) { g_h0v[i] = h0in[i]; g_h1v[i] = h0in[H + i]; }
        for (int i = tid; i < EMB; i += NTHR) g_embv[i] = 0.f;
    }
    float cA = 0.f, cB_ = 0.f;
    if (wid < 12 && lane == 0) { cA = c0in[j]; cB_ = c0in[H + j]; }

    unsigned target = 0;
    target += NBLK; grid_sync(target);

    for (int t = 0; t < T_STEPS; ++t) {
        // ---- phase A: layer-0 cell -------------------------------------------------
        const float* xin = inputVecs + (size_t)t * IN_DIM;
        for (int i = tid; i < CA; i += NTHR) {
            float v;
            if (i < IN_DIM)                v = __ldg(xin + i);
            else if (i < IN_DIM + EMB)     v = __ldcg(&g_embv[i - IN_DIM]);
            else if (i < IN_DIM + EMB + H) v = __ldcg(&g_h0v[i - IN_DIM - EMB]);
            else                           v = 0.f;
            sx[i] = v;
        }
        __syncthreads();
        if (wid < 12) {
            const __nv_bfloat16* base = g_WA + (size_t)j * CA;
            float a0, a1, a2, a3;
            dot4<7>(base, base + (size_t)H * CA, base + (size_t)(2 * H) * CA,
                    base + (size_t)(3 * H) * CA, sx, lane, a0, a1, a2, a3);
            a0 = wred(a0); a1 = wred(a1); a2 = wred(a2); a3 = wred(a3);
            if (lane == 0) {
                float gi = sigmoidf_(a0 + bi0[j] + bh0[j]);
                float gf = sigmoidf_(a1 + bi0[H + j] + bh0[H + j]);
                float gg = tanhf    (a2 + bi0[2 * H + j] + bh0[2 * H + j]);
                float go = sigmoidf_(a3 + bi0[3 * H + j] + bh0[3 * H + j]);
                cA = gf * cA + gi * gg;
                g_h0v[j] = go * tanhf(cA);
            }
        }
        target += NBLK; grid_sync(target);

        // ---- phase B: layer-1 cell -------------------------------------------------
        for (int i = tid; i < CB; i += NTHR)
            sx[i] = (i < H) ? __ldcg(&g_h0v[i]) : __ldcg(&g_h1v[i - H]);
        __syncthreads();
        if (wid < 12) {
            const __nv_bfloat16* base = g_WB + (size_t)j * CB;
            float a0, a1, a2, a3;
            dot4<12>(base, base + (size_t)H * CB, base + (size_t)(2 * H) * CB,
                     base + (size_t)(3 * H) * CB, sx, lane, a0, a1, a2, a3);
            a0 = wred(a0); a1 = wred(a1); a2 = wred(a2); a3 = wred(a3);
            if (lane == 0) {
                float gi = sigmoidf_(a0 + bi1[j] + bh1[j]);
                float gf = sigmoidf_(a1 + bi1[H + j] + bh1[H + j]);
                float gg = tanhf    (a2 + bi1[2 * H + j] + bh1[2 * H + j]);
                float go = sigmoidf_(a3 + bi1[3 * H + j] + bh1[3 * H + j]);
                cB_ = gf * cB_ + gi * gg;
                g_h1v[j] = go * tanhf(cB_);
            }
        }
        target += NBLK; grid_sync(target);

        // ---- phase C: z = W_hl @ h1n + b_hl ----------------------------------------
        for (int i = tid; i < H; i += NTHR) sx[i] = __ldcg(&g_h1v[i]);
        __syncthreads();
        if (wid < 8) {
            float a = wred(dot1<6>(g_WC + (size_t)rC * H, sx, lane));
            if (lane == 0) g_zv[rC] = a + bhl[rC];
        }
        target += NBLK; grid_sync(target);

        // ---- phase D (block 0): logits -> softmax -> output + emb ------------------
        if (bid == 0) {
            for (int i = tid; i < H2; i += NTHR) sx[i] = __ldcg(&g_zv[i]);
            __syncthreads();
            for (int r = wid; r < OUTD; r += 16) {
                float a = wred(dot1<4>(g_WO + (size_t)r * H2, sx, lane));
                if (lane == 0) sy[r] = a + bo[r];
            }
            __syncthreads();
            if (wid == 0) {
                float v0 = sy[lane], v1 = sy[lane + 32], v2 = sy[lane + 64], v3 = sy[lane + 96];
                float m = fmaxf(fmaxf(v0, v1), fmaxf(v2, v3));
                #pragma unroll
                for (int o = 16; o; o >>= 1) m = fmaxf(m, __shfl_xor_sync(0xffffffffu, m, o));
                float e0 = expf(v0 - m), e1 = expf(v1 - m), e2 = expf(v2 - m), e3 = expf(v3 - m);
                float s = wred(e0 + e1 + e2 + e3);
                float inv = 1.f / s;
                e0 *= inv; e1 *= inv; e2 *= inv; e3 *= inv;
                sy[lane] = e0; sy[lane + 32] = e1; sy[lane + 64] = e2; sy[lane + 96] = e3;
                float* op = out + (size_t)t * OUTD;
                op[lane] = e0; op[lane + 32] = e1; op[lane + 64] = e2; op[lane + 96] = e3;
            }
            __syncthreads();
            for (int r = wid; r < EMB; r += 16) {
                const __nv_bfloat16* w = g_WM + r * OUTD + lane * 4;
                uint2 wv = *reinterpret_cast<const uint2*>(w);
                float2 p0 = __bfloat1622float2(*reinterpret_cast<const __nv_bfloat162*>(&wv.x));
                float2 p1 = __bfloat1622float2(*reinterpret_cast<const __nv_bfloat162*>(&wv.y));
                float a = p0.x * sy[lane * 4] + p0.y * sy[lane * 4 + 1] +
                          p1.x * sy[lane * 4 + 2] + p1.y * sy[lane * 4 + 3];
                a = wred(a);
                if (lane == 0) g_embv[r] = a + bm[r];
            }
        }
        target += NBLK; grid_sync(target);
    }

    // end-of-launch reset: every block has observed the final release before arriving
    // here, so the last arriver can safely zero the counters for the next replay.
    if (tid == 0) {
        __threadfence();
        if (atomicAdd(&g_done, 1u) == NBLK - 1) {
            g_count = 0u;
            g_done = 0u;
            __threadfence();
        }
    }
}

// ---------------- launch --------------------------------------------------------------
extern "C" void kernel_launch(void* const* d_in, const int* in_sizes, int n_in,
                              void* d_out, int out_size) {
    const float* inputVecs = (const float*)d_in[0];
    const float* h0    = (const float*)d_in[1];
    const float* c0    = (const float*)d_in[2];
    const float* W_ih0 = (const float*)d_in[3];
    const float* W_hh0 = (const float*)d_in[4];
    const float* b_ih0 = (const float*)d_in[5];
    const float* b_hh0 = (const float*)d_in[6];
    const float* W_ih1 = (const float*)d_in[7];
    const float* W_hh1 = (const float*)d_in[8];
    const float* b_ih1 = (const float*)d_in[9];
    const float* b_hh1 = (const float*)d_in[10];
    const float* W_hl  = (const float*)d_in[11];
    const float* b_hl  = (const float*)d_in[12];
    const float* W_out = (const float*)d_in[13];
    const float* b_out = (const float*)d_in[14];
    const float* W_map = (const float*)d_in[15];
    const float* b_map = (const float*)d_in[16];

    pack_A<<<2048, 256>>>(W_ih0, W_hh0);
    pack_B<<<2048, 256>>>(W_ih1, W_hh1);
    pack_small<<<512, 256>>>(W_hl, W_out, W_map);
    lstm_main<<<NBLK, NTHR>>>(inputVecs, h0, c0,
                              b_ih0, b_hh0, b_ih1, b_hh1,
                              b_hl, b_out, b_map, (float*)d_out);
}

// round 2
// speedup vs baseline: 1.6860x; 1.6860x over previous
#include <cuda_runtime.h>
#include <cuda_bf16.h>

#define T_STEPS 2048
#define IN_DIM  118
#define EMB     128
#define H       1536
#define H4      6144
#define H2      1024
#define OUTD    128
#define CA      1792   // packed layer-0 row: hh(1536) | x(118) emb(128) | pad(10)
#define CB      3072   // packed layer-1 row: ih(1536) | hh(1536)
#define NBLK    128
#define NTHR    512

// ---------------- device-global scratch ----------------------------------------------
__device__ __align__(128) __nv_bfloat16 g_WA[(size_t)H4 * CA];   // ~21 MB
__device__ __align__(128) __nv_bfloat16 g_WB[(size_t)H4 * CB];   // ~37.7 MB
__device__ __align__(128) float g_WCB[(size_t)OUTD * H];         // W_comb = W_out@W_hl (fp32, 0.79MB)
__device__ float g_bcomb[OUTD];
__device__ float g_h0v[H];
__device__ float g_h1v[H];
__device__ float g_logits[OUTD];
__device__ unsigned g_count = 0;
__device__ unsigned g_done  = 0;

// ---------------- pack kernels --------------------------------------------------------
__global__ void pack_A(const float* __restrict__ Wih0, const float* __restrict__ Whh0) {
    size_t n = (size_t)H4 * CA;
    size_t stride = (size_t)gridDim.x * blockDim.x;
    for (size_t i = (size_t)blockIdx.x * blockDim.x + threadIdx.x; i < n; i += stride) {
        size_t r = i / CA;
        int c = (int)(i % CA);
        float v = 0.f;
        if (c < H)                 v = Whh0[r * H + c];
        else if (c < H + 246)      v = Wih0[r * 246 + (c - H)];
        g_WA[i] = __float2bfloat16(v);
    }
}

__global__ void pack_B(const float* __restrict__ Wih1, const float* __restrict__ Whh1) {
    size_t n = (size_t)H4 * CB;
    size_t stride = (size_t)gridDim.x * blockDim.x;
    for (size_t i = (size_t)blockIdx.x * blockDim.x + threadIdx.x; i < n; i += stride) {
        size_t r = i / CB;
        int c = (int)(i % CB);
        float v = (c < H) ? Wih1[r * H + c] : Whh1[r * H + (c - H)];
        g_WB[i] = __float2bfloat16(v);
    }
}

// W_comb[r,c] = sum_k W_out[r,k] * W_hl[k,c]   (128 x 1536, fp32)
__global__ void pack_comb(const float* __restrict__ Whl, const float* __restrict__ Wout) {
    int idx = blockIdx.x * blockDim.x + threadIdx.x;
    if (idx >= OUTD * H) return;
    int r = idx / H, c = idx % H;
    float s = 0.f;
    #pragma unroll 4
    for (int k = 0; k < H2; k++)
        s = fmaf(__ldg(Wout + r * H2 + k), __ldg(Whl + (size_t)k * H + c), s);
    g_WCB[idx] = s;
}

__global__ void pack_bcomb(const float* __restrict__ Wout, const float* __restrict__ bhl,
                           const float* __restrict__ bout) {
    int r = threadIdx.x;
    if (r >= OUTD) return;
    float s = 0.f;
    #pragma unroll 4
    for (int k = 0; k < H2; k++) s = fmaf(Wout[r * H2 + k], bhl[k], s);
    g_bcomb[r] = s + bout[r];
}

// ---------------- helpers -------------------------------------------------------------
__device__ __forceinline__ float wred(float a) {
    a += __shfl_xor_sync(0xffffffffu, a, 16);
    a += __shfl_xor_sync(0xffffffffu, a, 8);
    a += __shfl_xor_sync(0xffffffffu, a, 4);
    a += __shfl_xor_sync(0xffffffffu, a, 2);
    a += __shfl_xor_sync(0xffffffffu, a, 1);
    return a;
}

__device__ __forceinline__ float sigmoidf_(float x) { return 1.f / (1.f + expf(-x)); }

__device__ __forceinline__ void grid_sync(unsigned target) {
    __syncthreads();
    if (threadIdx.x == 0) {
        __threadfence();
        atomicAdd(&g_count, 1u);
        while (*(volatile unsigned*)&g_count < target) { }
        __threadfence();
    }
    __syncthreads();
}

#define FMA8(W, ACC) do {                                                                 \
    uint4 wv_ = __ldg(reinterpret_cast<const uint4*>((W) + k));                           \
    float2 p0_ = __bfloat1622float2(*reinterpret_cast<const __nv_bfloat162*>(&wv_.x));    \
    float2 p1_ = __bfloat1622float2(*reinterpret_cast<const __nv_bfloat162*>(&wv_.y));    \
    float2 p2_ = __bfloat1622float2(*reinterpret_cast<const __nv_bfloat162*>(&wv_.z));    \
    float2 p3_ = __bfloat1622float2(*reinterpret_cast<const __nv_bfloat162*>(&wv_.w));    \
    ACC = fmaf(x0.x, p0_.x, ACC); ACC = fmaf(x0.y, p0_.y, ACC);                           \
    ACC = fmaf(x0.z, p1_.x, ACC); ACC = fmaf(x0.w, p1_.y, ACC);                           \
    ACC = fmaf(x1.x, p2_.x, ACC); ACC = fmaf(x1.y, p2_.y, ACC);                           \
    ACC = fmaf(x1.z, p3_.x, ACC); ACC = fmaf(x1.w, p3_.y, ACC);                           \
} while (0)

// 3-row dot over NIT*256 columns; accumulates into A0..A2 (caller-initialized).
template <int NIT>
__device__ __forceinline__ void dot3(const __nv_bfloat16* __restrict__ w0,
                                     const __nv_bfloat16* __restrict__ w1,
                                     const __nv_bfloat16* __restrict__ w2,
                                     const float* __restrict__ sx, int lane,
                                     float& A0, float& A1, float& A2) {
    #pragma unroll 3
    for (int it = 0; it < NIT; ++it) {
        const int k = it * 256 + lane * 8;
        float4 x0 = *reinterpret_cast<const float4*>(sx + k);
        float4 x1 = *reinterpret_cast<const float4*>(sx + k + 4);
        FMA8(w0, A0);
        FMA8(w1, A1);
        FMA8(w2, A2);
    }
}

// ---------------- persistent main kernel ----------------------------------------------
__global__ void __launch_bounds__(NTHR, 1) lstm_main(
    const float* __restrict__ inputVecs,
    const float* __restrict__ h0in, const float* __restrict__ c0in,
    const float* __restrict__ bi0, const float* __restrict__ bh0,
    const float* __restrict__ bi1, const float* __restrict__ bh1,
    const float* __restrict__ Wmap, const float* __restrict__ bm,
    float* __restrict__ out) {
    __shared__ __align__(16) float sxh0[H];
    __shared__ __align__(16) float sxh1[H];
    __shared__ __align__(16) float sxx[256];
    __shared__ float sgate[48];
    __shared__ float sy[OUTD];
    __shared__ float semb[EMB];

    const int tid = threadIdx.x, lane = tid & 31, wid = tid >> 5, bid = blockIdx.x;

    // each warp owns 3 gate rows: idx = wid*3 + i; row = (idx/12)*H + bid*12 + idx%12
    const int i0 = wid * 3;
    const __nv_bfloat16 *wa[3], *wb[3];
    #pragma unroll
    for (int i = 0; i < 3; i++) {
        int idx = i0 + i;
        size_t r = (size_t)(idx / 12) * H + bid * 12 + (idx % 12);
        wa[i] = g_WA + r * CA;
        wb[i] = g_WB + r * CB;
    }

    // activation lanes: warp 0, lanes 0..11 own units j = bid*12 + lane
    const int j = bid * 12 + lane;
    float cA = 0.f, cB = 0.f;
    float baI = 0.f, baF = 0.f, baG = 0.f, baO = 0.f;
    float bbI = 0.f, bbF = 0.f, bbG = 0.f, bbO = 0.f;
    if (wid == 0 && lane < 12) {
        cA = c0in[j]; cB = c0in[H + j];
        baI = bi0[j] + bh0[j];             baF = bi0[H + j] + bh0[H + j];
        baG = bi0[2 * H + j] + bh0[2 * H + j]; baO = bi0[3 * H + j] + bh0[3 * H + j];
        bbI = bi1[j] + bh1[j];             bbF = bi1[H + j] + bh1[H + j];
        bbG = bi1[2 * H + j] + bh1[2 * H + j]; bbO = bi1[3 * H + j] + bh1[3 * H + j];
    }

    // prologue: prefetch hh partials from initial state; emb = 0 (local)
    for (int i = tid; i < H; i += NTHR) { sxh0[i] = __ldg(h0in + i); sxh1[i] = __ldg(h0in + H + i); }
    for (int i = tid; i < EMB; i += NTHR) semb[i] = 0.f;
    __syncthreads();
    float pA0 = 0.f, pA1 = 0.f, pA2 = 0.f, pB0 = 0.f, pB1 = 0.f, pB2 = 0.f;
    dot3<6>(wa[0], wa[1], wa[2], sxh0, lane, pA0, pA1, pA2);
    dot3<6>(wb[0] + H, wb[1] + H, wb[2] + H, sxh1, lane, pB0, pB1, pB2);
    __syncthreads();

    unsigned target = 0;

    for (int t = 0; t < T_STEPS; ++t) {
        // ---- phase A (local): x/emb part + prefetched hh partial -> h0n -------------
        const float* xin = inputVecs + (size_t)t * IN_DIM;
        if (tid < 256) {
            float v = 0.f;
            if (tid < IN_DIM)      v = __ldg(xin + tid);
            else if (tid < 246)    v = semb[tid - IN_DIM];
            sxx[tid] = v;
        }
        __syncthreads();
        {
            float a0 = pA0, a1 = pA1, a2 = pA2;
            dot3<1>(wa[0] + H, wa[1] + H, wa[2] + H, sxx, lane, a0, a1, a2);
            a0 = wred(a0); a1 = wred(a1); a2 = wred(a2);
            if (lane == 0) { sgate[i0] = a0; sgate[i0 + 1] = a1; sgate[i0 + 2] = a2; }
        }
        __syncthreads();
        if (wid == 0 && lane < 12) {
            float gi = sigmoidf_(sgate[lane] + baI);
            float gf = sigmoidf_(sgate[12 + lane] + baF);
            float gg = tanhf    (sgate[24 + lane] + baG);
            float go = sigmoidf_(sgate[36 + lane] + baO);
            cA = gf * cA + gi * gg;
            g_h0v[j] = go * tanhf(cA);
        }
        target += NBLK; grid_sync(target);                       // bar1: h0n ready

        // ---- phase B: ih1 part + prefetched hh1 partial -> h1n ----------------------
        for (int i = tid; i < H; i += NTHR) sxh0[i] = __ldcg(&g_h0v[i]);
        __syncthreads();
        {
            float a0 = pB0, a1 = pB1, a2 = pB2;
            dot3<6>(wb[0], wb[1], wb[2], sxh0, lane, a0, a1, a2);
            a0 = wred(a0); a1 = wred(a1); a2 = wred(a2);
            if (lane == 0) { sgate[i0] = a0; sgate[i0 + 1] = a1; sgate[i0 + 2] = a2; }
        }
        __syncthreads();
        if (wid == 0 && lane < 12) {
            float gi = sigmoidf_(sgate[lane] + bbI);
            float gf = sigmoidf_(sgate[12 + lane] + bbF);
            float gg = tanhf    (sgate[24 + lane] + bbG);
            float go = sigmoidf_(sgate[36 + lane] + bbO);
            cB = gf * cB + gi * gg;
            g_h1v[j] = go * tanhf(cB);
        }
        target += NBLK; grid_sync(target);                       // bar2: h1n ready

        // ---- phase E: this block computes logits[bid] = W_comb[bid]·h1n + b --------
        for (int i = tid; i < H; i += NTHR) sxh1[i] = __ldcg(&g_h1v[i]);
        __syncthreads();
        if (wid < 12) {
            int c = wid * 128 + lane * 4;
            float4 x = *reinterpret_cast<const float4*>(sxh1 + c);
            float4 w = *reinterpret_cast<const float4*>(g_WCB + (size_t)bid * H + c);
            float a = x.x * w.x + x.y * w.y + x.z * w.z + x.w * w.w;
            c += 12 * 128;   // cols 1536 covered as 12*128, done; (H==1536 exactly)
            a = wred(a);
            if (lane == 0) sgate[wid] = a;
        }
        __syncthreads();
        if (tid == 0) {
            float s = 0.f;
            #pragma unroll
            for (int i = 0; i < 12; i++) s += sgate[i];
            g_logits[bid] = s + g_bcomb[bid];
        }
        target += NBLK; grid_sync(target);                       // bar3: logits ready

        // ---- slot4 (local, no trailing grid barrier): softmax + emb + prefetch -----
        if (tid < OUTD) sy[tid] = __ldcg(&g_logits[tid]);
        __syncthreads();
        if (wid == 0) {
            float v0 = sy[lane], v1 = sy[lane + 32], v2 = sy[lane + 64], v3 = sy[lane + 96];
            float m = fmaxf(fmaxf(v0, v1), fmaxf(v2, v3));
            #pragma unroll
            for (int o = 16; o; o >>= 1) m = fmaxf(m, __shfl_xor_sync(0xffffffffu, m, o));
            float e0 = expf(v0 - m), e1 = expf(v1 - m), e2 = expf(v2 - m), e3 = expf(v3 - m);
            float s = wred(e0 + e1 + e2 + e3);
            float inv = 1.f / s;
            e0 *= inv; e1 *= inv; e2 *= inv; e3 *= inv;
            sy[lane] = e0; sy[lane + 32] = e1; sy[lane + 64] = e2; sy[lane + 96] = e3;
            if (bid == 0) {
                float* op = out + (size_t)t * OUTD;
                op[lane] = e0; op[lane + 32] = e1; op[lane + 64] = e2; op[lane + 96] = e3;
            }
        }
        __syncthreads();
        for (int r = wid; r < EMB; r += 16) {
            float4 w = *reinterpret_cast<const float4*>(Wmap + r * OUTD + lane * 4);
            float a = w.x * sy[lane * 4] + w.y * sy[lane * 4 + 1] +
                      w.z * sy[lane * 4 + 2] + w.w * sy[lane * 4 + 3];
            a = wred(a);
            if (lane == 0) semb[r] = a + bm[r];
        }
        // prefetch next step's hh partials (sxh0 = h0n(t), sxh1 = h1n(t), both local)
        pA0 = pA1 = pA2 = 0.f;
        dot3<6>(wa[0], wa[1], wa[2], sxh0, lane, pA0, pA1, pA2);
        pB0 = pB1 = pB2 = 0.f;
        dot3<6>(wb[0] + H, wb[1] + H, wb[2] + H, sxh1, lane, pB0, pB1, pB2);
        __syncthreads();   // semb visible to phase A fill of t+1
    }

    // end-of-launch reset of barrier counters (last arriver)
    if (tid == 0) {
        __threadfence();
        if (atomicAdd(&g_done, 1u) == NBLK - 1) {
            g_count = 0u;
            g_done = 0u;
            __threadfence();
        }
    }
}

// ---------------- launch --------------------------------------------------------------
extern "C" void kernel_launch(void* const* d_in, const int* in_sizes, int n_in,
                              void* d_out, int out_size) {
    const float* inputVecs = (const float*)d_in[0];
    const float* h0    = (const float*)d_in[1];
    const float* c0    = (const float*)d_in[2];
    const float* W_ih0 = (const float*)d_in[3];
    const float* W_hh0 = (const float*)d_in[4];
    const float* b_ih0 = (const float*)d_in[5];
    const float* b_hh0 = (const float*)d_in[6];
    const float* W_ih1 = (const float*)d_in[7];
    const float* W_hh1 = (const float*)d_in[8];
    const float* b_ih1 = (const float*)d_in[9];
    const float* b_hh1 = (const float*)d_in[10];
    const float* W_hl  = (const float*)d_in[11];
    const float* b_hl  = (const float*)d_in[12];
    const float* W_out = (const float*)d_in[13];
    const float* b_out = (const float*)d_in[14];
    const float* W_map = (const float*)d_in[15];
    const float* b_map = (const float*)d_in[16];

    pack_A<<<1024, 256>>>(W_ih0, W_hh0);
    pack_B<<<1024, 256>>>(W_ih1, W_hh1);
    pack_comb<<<(OUTD * H + 255) / 256, 256>>>(W_hl, W_out);
    pack_bcomb<<<1, 128>>>(W_out, b_hl, b_out);
    lstm_main<<<NBLK, NTHR>>>(inputVecs, h0, c0,
                              b_ih0, b_hh0, b_ih1, b_hh1,
                              W_map, b_map, (float*)d_out);
}

// round 3
// speedup vs baseline: 1.9007x; 1.1274x over previous
#include <cuda_runtime.h>
#include <cuda_bf16.h>

#define T_STEPS 2048
#define IN_DIM  118
#define EMB     128
#define H       1536
#define H4      6144
#define H2      1024
#define OUTD    128
#define CA      1792   // packed layer-0 row cols: hh(1536) | x(118) emb(128) | pad(10)
#define CB      3072   // packed layer-1 row cols: ih(1536) | hh(1536)
#define CAW     (CA/2) // 896 words
#define CBW     (CB/2) // 1536 words
#define NBLK    128
#define NTHR    512

// ---------------- device-global scratch ----------------------------------------------
__device__ __align__(128) unsigned g_WA[(size_t)H4 * CAW];   // ~21 MB (bf16 pairs)
__device__ __align__(128) unsigned g_WB[(size_t)H4 * CBW];   // ~37.7 MB
__device__ __align__(128) float g_WCB[(size_t)OUTD * H];     // W_comb = W_out@W_hl (fp32)
__device__ float g_bcomb[OUTD];
__device__ __align__(16) float g_h0v[H];
__device__ __align__(16) float g_h1v[H];
__device__ float g_logits[OUTD];
__device__ unsigned g_count = 0;
__device__ unsigned g_done  = 0;

// ---------------- bf16-pair packing with hi-compensation ------------------------------
// Reader decodes: lo = as_float(w<<16)  (exact bf16 of w_lo)
//                 hi = as_float(w)      (hi bf16 bits with lo16 as mantissa tail)
// Pack picks hi bits so that as_float(w) is as close as possible to the true w_hi.
__device__ __forceinline__ unsigned pack2(float wlo, float whi) {
    unsigned lo16 = (unsigned)__bfloat16_as_ushort(__float2bfloat16(wlo));
    unsigned base = __float_as_uint(whi) & 0xffff0000u;
    unsigned c0 = base | lo16, c1 = (base + 0x10000u) | lo16, c2 = (base - 0x10000u) | lo16;
    float d0 = fabsf(__uint_as_float(c0) - whi);
    float d1 = fabsf(__uint_as_float(c1) - whi);
    float d2 = fabsf(__uint_as_float(c2) - whi);
    unsigned best = c0; float bd = d0;
    if (d1 < bd) { bd = d1; best = c1; }
    if (d2 < bd) { best = c2; }
    return best;
}

__device__ __forceinline__ float srcA(const float* Wih0, const float* Whh0, size_t r, int c) {
    if (c < H)            return Whh0[r * H + c];
    if (c < H + 246)      return Wih0[r * 246 + (c - H)];
    return 0.f;
}

__global__ void pack_A(const float* __restrict__ Wih0, const float* __restrict__ Whh0) {
    size_t n = (size_t)H4 * CAW;
    size_t stride = (size_t)gridDim.x * blockDim.x;
    for (size_t i = (size_t)blockIdx.x * blockDim.x + threadIdx.x; i < n; i += stride) {
        size_t r = i / CAW;
        int c = 2 * (int)(i % CAW);
        g_WA[i] = pack2(srcA(Wih0, Whh0, r, c), srcA(Wih0, Whh0, r, c + 1));
    }
}

__global__ void pack_B(const float* __restrict__ Wih1, const float* __restrict__ Whh1) {
    size_t n = (size_t)H4 * CBW;
    size_t stride = (size_t)gridDim.x * blockDim.x;
    for (size_t i = (size_t)blockIdx.x * blockDim.x + threadIdx.x; i < n; i += stride) {
        size_t r = i / CBW;
        int c = 2 * (int)(i % CBW);
        float lo = (c < H)     ? Wih1[r * H + c]     : Whh1[r * H + (c - H)];
        float hi = (c + 1 < H) ? Wih1[r * H + c + 1] : Whh1[r * H + (c + 1 - H)];
        g_WB[i] = pack2(lo, hi);
    }
}

// W_comb[r,c] = sum_k W_out[r,k] * W_hl[k,c]   (128 x 1536, fp32)
__global__ void pack_comb(const float* __restrict__ Whl, const float* __restrict__ Wout) {
    int idx = blockIdx.x * blockDim.x + threadIdx.x;
    if (idx >= OUTD * H) return;
    int r = idx / H, c = idx % H;
    float s = 0.f;
    #pragma unroll 4
    for (int k = 0; k < H2; k++)
        s = fmaf(__ldg(Wout + r * H2 + k), __ldg(Whl + (size_t)k * H + c), s);
    g_WCB[idx] = s;
}

__device__ __forceinline__ float wred(float a) {
    a += __shfl_xor_sync(0xffffffffu, a, 16);
    a += __shfl_xor_sync(0xffffffffu, a, 8);
    a += __shfl_xor_sync(0xffffffffu, a, 4);
    a += __shfl_xor_sync(0xffffffffu, a, 2);
    a += __shfl_xor_sync(0xffffffffu, a, 1);
    return a;
}

__global__ void pack_bcomb(const float* __restrict__ Wout, const float* __restrict__ bhl,
                           const float* __restrict__ bout) {
    __shared__ float red[8];
    int r = blockIdx.x;
    float s = 0.f;
    for (int k = threadIdx.x; k < H2; k += 256)
        s = fmaf(Wout[r * H2 + k], bhl[k], s);
    s = wred(s);
    if ((threadIdx.x & 31) == 0) red[threadIdx.x >> 5] = s;
    __syncthreads();
    if (threadIdx.x == 0) {
        float t = 0.f;
        #pragma unroll
        for (int i = 0; i < 8; i++) t += red[i];
        g_bcomb[r] = t + bout[r];
    }
}

// ---------------- core math -----------------------------------------------------------
__device__ __forceinline__ float sigmoidf_(float x) { return 1.f / (1.f + expf(-x)); }

// packed bf16-pair FMA: acc(pair) += decode(w) * (x0,x1)   [1 SHL + 1 FFMA2]
__device__ __forceinline__ void bffma2(float& a0, float& a1, unsigned w, float x0, float x1) {
    asm("{\n\t"
        ".reg .b32 lo;\n\t"
        ".reg .b64 wp, xp, ap;\n\t"
        "shl.b32 lo, %2, 16;\n\t"
        "mov.b64 wp, {lo, %2};\n\t"
        "mov.b64 xp, {%3, %4};\n\t"
        "mov.b64 ap, {%0, %1};\n\t"
        "fma.rn.f32x2 ap, wp, xp, ap;\n\t"
        "mov.b64 {%0, %1}, ap;\n\t"
        "}" : "+f"(a0), "+f"(a1) : "r"(w), "f"(x0), "f"(x1));
}

// NR-row dot over NIT*256 columns, accumulating into A (caller-initialized).
template <int NR, int NIT>
__device__ __forceinline__ void dotp(const unsigned* const (&w)[NR],
                                     const float* __restrict__ sx, int lane,
                                     float2 (&A)[NR]) {
    #pragma unroll 2
    for (int it = 0; it < NIT; ++it) {
        const int kf = it * 256 + lane * 8;
        const int kw = it * 128 + lane * 4;
        float4 x0 = *reinterpret_cast<const float4*>(sx + kf);
        float4 x1 = *reinterpret_cast<const float4*>(sx + kf + 4);
        #pragma unroll
        for (int r = 0; r < NR; ++r) {
            uint4 wv = __ldg(reinterpret_cast<const uint4*>(w[r] + kw));
            bffma2(A[r].x, A[r].y, wv.x, x0.x, x0.y);
            bffma2(A[r].x, A[r].y, wv.y, x0.z, x0.w);
            bffma2(A[r].x, A[r].y, wv.z, x1.x, x1.y);
            bffma2(A[r].x, A[r].y, wv.w, x1.z, x1.w);
        }
    }
}

__device__ __forceinline__ void grid_sync(unsigned target) {
    __syncthreads();
    if (threadIdx.x == 0) {
        asm volatile("red.release.gpu.global.add.u32 [%0], 1;" :: "l"(&g_count) : "memory");
        unsigned v;
        do {
            asm volatile("ld.acquire.gpu.global.u32 %0, [%1];" : "=r"(v) : "l"(&g_count) : "memory");
        } while (v < target);
    }
    __syncthreads();
}

// ---------------- persistent main kernel ----------------------------------------------
__global__ void __launch_bounds__(NTHR, 1) lstm_main(
    const float* __restrict__ inputVecs,
    const float* __restrict__ h0in, const float* __restrict__ c0in,
    const float* __restrict__ bi0, const float* __restrict__ bh0,
    const float* __restrict__ bi1, const float* __restrict__ bh1,
    const float* __restrict__ Wmap, const float* __restrict__ bm,
    float* __restrict__ out) {
    __shared__ __align__(16) float sxh0[H];
    __shared__ __align__(16) float sxh1[H];
    __shared__ __align__(16) float sxx[256];
    __shared__ float sgate[48];
    __shared__ float sy[OUTD];
    __shared__ float semb[EMB];

    const int tid = threadIdx.x, lane = tid & 31, wid = tid >> 5, bid = blockIdx.x;

    // each warp owns 3 gate rows: idx = wid*3+i; row = (idx/12)*H + bid*12 + idx%12
    const int i0 = wid * 3;
    const unsigned *waH[3], *waX[3], *wbI[3], *wbH[3];
    #pragma unroll
    for (int i = 0; i < 3; i++) {
        int idx = i0 + i;
        size_t r = (size_t)(idx / 12) * H + bid * 12 + (idx % 12);
        waH[i] = g_WA + r * CAW;            // layer0 hh  (cols 0..1535)
        waX[i] = g_WA + r * CAW + H / 2;    // layer0 x/emb (cols 1536..1791)
        wbI[i] = g_WB + r * CBW;            // layer1 ih  (cols 0..1535)
        wbH[i] = g_WB + r * CBW + H / 2;    // layer1 hh  (cols 1536..3071)
    }

    // activation lanes: warp 0, lanes 0..11 own units j = bid*12 + lane
    const int j = bid * 12 + lane;
    float cA = 0.f, cB = 0.f;
    float baI = 0.f, baF = 0.f, baG = 0.f, baO = 0.f;
    float bbI = 0.f, bbF = 0.f, bbG = 0.f, bbO = 0.f;
    if (wid == 0 && lane < 12) {
        cA = c0in[j]; cB = c0in[H + j];
        baI = bi0[j] + bh0[j];                 baF = bi0[H + j] + bh0[H + j];
        baG = bi0[2 * H + j] + bh0[2 * H + j]; baO = bi0[3 * H + j] + bh0[3 * H + j];
        bbI = bi1[j] + bh1[j];                 bbF = bi1[H + j] + bh1[H + j];
        bbG = bi1[2 * H + j] + bh1[2 * H + j]; bbO = bi1[3 * H + j] + bh1[3 * H + j];
    }

    // prologue: hh partials from initial state; emb = 0
    for (int i = tid; i < H; i += NTHR) { sxh0[i] = __ldg(h0in + i); sxh1[i] = __ldg(h0in + H + i); }
    for (int i = tid; i < EMB; i += NTHR) semb[i] = 0.f;
    __syncthreads();
    float2 pA[3] = {{0,0},{0,0},{0,0}}, pB[3] = {{0,0},{0,0},{0,0}};
    dotp<3, 6>(waH, sxh0, lane, pA);
    dotp<3, 6>(wbH, sxh1, lane, pB);
    __syncthreads();

    unsigned target = 0;

    for (int t = 0; t < T_STEPS; ++t) {
        // ---- phase A (block-local): x/emb part + prefetched hh partial -> h0n -------
        const float* xin = inputVecs + (size_t)t * IN_DIM;
        if (tid < 256) {
            float v = 0.f;
            if (tid < IN_DIM)   v = __ldg(xin + tid);
            else if (tid < 246) v = semb[tid - IN_DIM];
            sxx[tid] = v;
        }
        __syncthreads();
        {
            float2 a[3] = { pA[0], pA[1], pA[2] };
            dotp<3, 1>(waX, sxx, lane, a);
            #pragma unroll
            for (int i = 0; i < 3; i++) {
                float s = wred(a[i].x + a[i].y);
                if (lane == 0) sgate[i0 + i] = s;
            }
        }
        __syncthreads();
        if (wid == 0 && lane < 12) {
            float gi = sigmoidf_(sgate[lane] + baI);
            float gf = sigmoidf_(sgate[12 + lane] + baF);
            float gg = tanhf    (sgate[24 + lane] + baG);
            float go = sigmoidf_(sgate[36 + lane] + baO);
            cA = gf * cA + gi * gg;
            g_h0v[j] = go * tanhf(cA);
        }
        target += NBLK; grid_sync(target);                       // bar1: h0n ready

        // ---- slot B: fused  (B-ih dot -> gates1)  +  (A-hh prefetch for t+1) --------
        if (tid < 384)
            reinterpret_cast<float4*>(sxh0)[tid] =
                __ldcg(reinterpret_cast<const float4*>(g_h0v) + tid);
        __syncthreads();
        {
            const unsigned* w6[6] = { wbI[0], wbI[1], wbI[2], waH[0], waH[1], waH[2] };
            float2 a[6] = { pB[0], pB[1], pB[2], {0,0}, {0,0}, {0,0} };
            dotp<6, 6>(w6, sxh0, lane, a);
            #pragma unroll
            for (int i = 0; i < 3; i++) {
                float s = wred(a[i].x + a[i].y);
                if (lane == 0) sgate[i0 + i] = s;
            }
            pA[0] = a[3]; pA[1] = a[4]; pA[2] = a[5];
        }
        __syncthreads();
        if (wid == 0 && lane < 12) {
            float gi = sigmoidf_(sgate[lane] + bbI);
            float gf = sigmoidf_(sgate[12 + lane] + bbF);
            float gg = tanhf    (sgate[24 + lane] + bbG);
            float go = sigmoidf_(sgate[36 + lane] + bbO);
            cB = gf * cB + gi * gg;
            g_h1v[j] = go * tanhf(cB);
        }
        target += NBLK; grid_sync(target);                       // bar2: h1n ready

        // ---- slot E: fused  (logit[bid])  +  (B-hh prefetch for t+1) ----------------
        if (tid < 384)
            reinterpret_cast<float4*>(sxh1)[tid] =
                __ldcg(reinterpret_cast<const float4*>(g_h1v) + tid);
        __syncthreads();
        pB[0] = make_float2(0.f, 0.f); pB[1] = make_float2(0.f, 0.f); pB[2] = make_float2(0.f, 0.f);
        dotp<3, 6>(wbH, sxh1, lane, pB);
        if (wid < 12) {
            int c = wid * 128 + lane * 4;
            float4 x = *reinterpret_cast<const float4*>(sxh1 + c);
            float4 w = __ldg(reinterpret_cast<const float4*>(g_WCB + (size_t)bid * H + c));
            float a = x.x * w.x + x.y * w.y + x.z * w.z + x.w * w.w;
            a = wred(a);
            if (lane == 0) sgate[wid] = a;
        }
        __syncthreads();
        if (tid == 0) {
            float s = 0.f;
            #pragma unroll
            for (int i = 0; i < 12; i++) s += sgate[i];
            g_logits[bid] = s + g_bcomb[bid];
        }
        target += NBLK; grid_sync(target);                       // bar3: logits ready

        // ---- slot4 (block-local): softmax + emb -------------------------------------
        if (tid < OUTD) sy[tid] = __ldcg(&g_logits[tid]);
        __syncthreads();
        if (wid == 0) {
            float v0 = sy[lane], v1 = sy[lane + 32], v2 = sy[lane + 64], v3 = sy[lane + 96];
            float m = fmaxf(fmaxf(v0, v1), fmaxf(v2, v3));
            #pragma unroll
            for (int o = 16; o; o >>= 1) m = fmaxf(m, __shfl_xor_sync(0xffffffffu, m, o));
            float e0 = expf(v0 - m), e1 = expf(v1 - m), e2 = expf(v2 - m), e3 = expf(v3 - m);
            float s = wred(e0 + e1 + e2 + e3);
            float inv = 1.f / s;
            e0 *= inv; e1 *= inv; e2 *= inv; e3 *= inv;
            sy[lane] = e0; sy[lane + 32] = e1; sy[lane + 64] = e2; sy[lane + 96] = e3;
            if (bid == 0) {
                float* op = out + (size_t)t * OUTD;
                op[lane] = e0; op[lane + 32] = e1; op[lane + 64] = e2; op[lane + 96] = e3;
            }
        }
        __syncthreads();
        for (int r = wid; r < EMB; r += 16) {
            float4 w = __ldg(reinterpret_cast<const float4*>(Wmap + r * OUTD + lane * 4));
            float a = w.x * sy[lane * 4] + w.y * sy[lane * 4 + 1] +
                      w.z * sy[lane * 4 + 2] + w.w * sy[lane * 4 + 3];
            a = wred(a);
            if (lane == 0) semb[r] = a + bm[r];
        }
        __syncthreads();   // semb visible to phase A fill of t+1
    }

    // end-of-launch reset of barrier counters (last arriver), for graph replay
    if (tid == 0) {
        __threadfence();
        if (atomicAdd(&g_done, 1u) == NBLK - 1) {
            g_count = 0u;
            g_done = 0u;
            __threadfence();
        }
    }
}

// ---------------- launch --------------------------------------------------------------
extern "C" void kernel_launch(void* const* d_in, const int* in_sizes, int n_in,
                              void* d_out, int out_size) {
    const float* inputVecs = (const float*)d_in[0];
    const float* h0    = (const float*)d_in[1];
    const float* c0    = (const float*)d_in[2];
    const float* W_ih0 = (const float*)d_in[3];
    const float* W_hh0 = (const float*)d_in[4];
    const float* b_ih0 = (const float*)d_in[5];
    const float* b_hh0 = (const float*)d_in[6];
    const float* W_ih1 = (const float*)d_in[7];
    const float* W_hh1 = (const float*)d_in[8];
    const float* b_ih1 = (const float*)d_in[9];
    const float* b_hh1 = (const float*)d_in[10];
    const float* W_hl  = (const float*)d_in[11];
    const float* b_hl  = (const float*)d_in[12];
    const float* W_out = (const float*)d_in[13];
    const float* b_out = (const float*)d_in[14];
    const float* W_map = (const float*)d_in[15];
    const float* b_map = (const float*)d_in[16];

    pack_A<<<1024, 256>>>(W_ih0, W_hh0);
    pack_B<<<1024, 256>>>(W_ih1, W_hh1);
    pack_comb<<<(OUTD * H + 255) / 256, 256>>>(W_hl, W_out);
    pack_bcomb<<<OUTD, 256>>>(W_out, b_hl, b_out);
    lstm_main<<<NBLK, NTHR>>>(inputVecs, h0, c0,
                              b_ih0, b_hh0, b_ih1, b_hh1,
                              W_map, b_map, (float*)d_out);
}

// round 4
// speedup vs baseline: 2.0578x; 1.0826x over previous
#include <cuda_runtime.h>
#include <cuda_bf16.h>

#define T_STEPS 2048
#define IN_DIM  118
#define EMB     128
#define H       1536
#define H4      6144
#define H2      1024
#define OUTD    128
#define CA      1792   // layer-0 row cols: hh(1536) | x(118) emb(128) | pad(10)
#define CB      3072   // layer-1 row cols: ih(1536) | hh(1536)
#define CAW     (CA/2)
#define CBW     (CB/2)
#define NBLK    128
#define NTHR    512

// ---------------- device-global scratch ----------------------------------------------
__device__ __align__(128) unsigned g_WA[(size_t)H4 * CAW];   // ~21 MB (bf16 pairs)
__device__ __align__(128) unsigned g_WB[(size_t)H4 * CBW];   // ~37.7 MB
__device__ __align__(128) float g_WCB[(size_t)OUTD * H];     // W_comb = W_out@W_hl (fp32)
__device__ float g_bcomb[OUTD];
__device__ __align__(16) float g_h0v[H];
__device__ __align__(16) float g_h1v[H];
__device__ float g_logits[OUTD];
__device__ unsigned g_count = 0;
__device__ unsigned g_done  = 0;

// ---------------- bf16-pair packing with hi-compensation ------------------------------
__device__ __forceinline__ unsigned pack2(float wlo, float whi) {
    unsigned lo16 = (unsigned)__bfloat16_as_ushort(__float2bfloat16(wlo));
    unsigned base = __float_as_uint(whi) & 0xffff0000u;
    unsigned c0 = base | lo16, c1 = (base + 0x10000u) | lo16, c2 = (base - 0x10000u) | lo16;
    float d0 = fabsf(__uint_as_float(c0) - whi);
    float d1 = fabsf(__uint_as_float(c1) - whi);
    float d2 = fabsf(__uint_as_float(c2) - whi);
    unsigned best = c0; float bd = d0;
    if (d1 < bd) { bd = d1; best = c1; }
    if (d2 < bd) { best = c2; }
    return best;
}

__device__ __forceinline__ float srcA(const float* Wih0, const float* Whh0, size_t r, int c) {
    if (c < H)       return Whh0[r * H + c];
    if (c < H + 246) return Wih0[r * 246 + (c - H)];
    return 0.f;
}

// Single mega-pack kernel: covers WA, WB, W_comb, b_comb in one launch
// (keeps the per-call launch count at 2 so ncu -s 5 lands on lstm_main).
__global__ void pack_all(const float* __restrict__ Wih0, const float* __restrict__ Whh0,
                         const float* __restrict__ Wih1, const float* __restrict__ Whh1,
                         const float* __restrict__ Whl,  const float* __restrict__ Wout,
                         const float* __restrict__ bhl,  const float* __restrict__ bout) {
    const size_t nA = (size_t)H4 * CAW;
    const size_t nB = (size_t)H4 * CBW;
    const size_t nC = (size_t)OUTD * H;
    const size_t total = nA + nB + nC + OUTD;
    size_t stride = (size_t)gridDim.x * blockDim.x;
    for (size_t i = (size_t)blockIdx.x * blockDim.x + threadIdx.x; i < total; i += stride) {
        if (i < nA) {
            size_t r = i / CAW;
            int c = 2 * (int)(i % CAW);
            g_WA[i] = pack2(srcA(Wih0, Whh0, r, c), srcA(Wih0, Whh0, r, c + 1));
        } else if (i < nA + nB) {
            size_t k = i - nA;
            size_t r = k / CBW;
            int c = 2 * (int)(k % CBW);
            float lo = (c < H)     ? Wih1[r * H + c]     : Whh1[r * H + (c - H)];
            float hi = (c + 1 < H) ? Wih1[r * H + c + 1] : Whh1[r * H + (c + 1 - H)];
            g_WB[k] = pack2(lo, hi);
        } else if (i < nA + nB + nC) {
            size_t k = i - nA - nB;
            int r = (int)(k / H), c = (int)(k % H);
            float s = 0.f;
            #pragma unroll 4
            for (int kk = 0; kk < H2; kk++)
                s = fmaf(__ldg(Wout + r * H2 + kk), __ldg(Whl + (size_t)kk * H + c), s);
            g_WCB[k] = s;
        } else {
            int r = (int)(i - nA - nB - nC);
            float s = 0.f;
            #pragma unroll 4
            for (int kk = 0; kk < H2; kk++) s = fmaf(Wout[r * H2 + kk], bhl[kk], s);
            g_bcomb[r] = s + bout[r];
        }
    }
}

// ---------------- core math -----------------------------------------------------------
__device__ __forceinline__ float wred(float a) {
    a += __shfl_xor_sync(0xffffffffu, a, 16);
    a += __shfl_xor_sync(0xffffffffu, a, 8);
    a += __shfl_xor_sync(0xffffffffu, a, 4);
    a += __shfl_xor_sync(0xffffffffu, a, 2);
    a += __shfl_xor_sync(0xffffffffu, a, 1);
    return a;
}

__device__ __forceinline__ float sigmoidf_(float x) { return 1.f / (1.f + expf(-x)); }

// packed bf16-pair FMA: acc(pair) += decode(w) * (x0,x1)   [1 SHL + 1 FFMA2]
__device__ __forceinline__ void bffma2(float& a0, float& a1, unsigned w, float x0, float x1) {
    asm("{\n\t"
        ".reg .b32 lo;\n\t"
        ".reg .b64 wp, xp, ap;\n\t"
        "shl.b32 lo, %2, 16;\n\t"
        "mov.b64 wp, {lo, %2};\n\t"
        "mov.b64 xp, {%3, %4};\n\t"
        "mov.b64 ap, {%0, %1};\n\t"
        "fma.rn.f32x2 ap, wp, xp, ap;\n\t"
        "mov.b64 {%0, %1}, ap;\n\t"
        "}" : "+f"(a0), "+f"(a1) : "r"(w), "f"(x0), "f"(x1));
}

// NR-row dot over NIT*256 columns, accumulating into A (caller-initialized).
template <int NR, int NIT>
__device__ __forceinline__ void dotp(const unsigned* const (&w)[NR],
                                     const float* __restrict__ sx, int lane,
                                     float2 (&A)[NR]) {
    #pragma unroll 2
    for (int it = 0; it < NIT; ++it) {
        const int kf = it * 256 + lane * 8;
        const int kw = it * 128 + lane * 4;
        float4 x0 = *reinterpret_cast<const float4*>(sx + kf);
        float4 x1 = *reinterpret_cast<const float4*>(sx + kf + 4);
        #pragma unroll
        for (int r = 0; r < NR; ++r) {
            uint4 wv = __ldg(reinterpret_cast<const uint4*>(w[r] + kw));
            bffma2(A[r].x, A[r].y, wv.x, x0.x, x0.y);
            bffma2(A[r].x, A[r].y, wv.y, x0.z, x0.w);
            bffma2(A[r].x, A[r].y, wv.z, x1.x, x1.y);
            bffma2(A[r].x, A[r].y, wv.w, x1.z, x1.w);
        }
    }
}

// split grid barrier: arrive (release) / wait (acquire-poll)
__device__ __forceinline__ void bar_arrive() {
    __syncthreads();
    if (threadIdx.x == 0)
        asm volatile("red.release.gpu.global.add.u32 [%0], 1;" :: "l"(&g_count) : "memory");
}
__device__ __forceinline__ void bar_wait(unsigned target) {
    if (threadIdx.x == 0) {
        unsigned v;
        do {
            asm volatile("ld.acquire.gpu.global.u32 %0, [%1];" : "=r"(v) : "l"(&g_count) : "memory");
        } while (v < target);
    }
    __syncthreads();
}

// ---------------- persistent main kernel ----------------------------------------------
__global__ void __launch_bounds__(NTHR, 1) lstm_main(
    const float* __restrict__ inputVecs,
    const float* __restrict__ h0in, const float* __restrict__ c0in,
    const float* __restrict__ bi0, const float* __restrict__ bh0,
    const float* __restrict__ bi1, const float* __restrict__ bh1,
    const float* __restrict__ Wmap, const float* __restrict__ bm,
    float* __restrict__ out) {
    __shared__ __align__(16) float sxh0[H];
    __shared__ __align__(16) float sxh1[H];
    __shared__ __align__(16) float sxx[256];
    __shared__ float sgate[48];
    __shared__ float sy[OUTD];
    __shared__ float semb[EMB];

    const int tid = threadIdx.x, lane = tid & 31, wid = tid >> 5, bid = blockIdx.x;

    // each warp owns 3 gate rows: idx = wid*3+i; row = (idx/12)*H + bid*12 + idx%12
    const int i0 = wid * 3;
    const unsigned *waH[3], *waX[3], *wbI[3], *wbH[3], *wbH2[3];
    #pragma unroll
    for (int i = 0; i < 3; i++) {
        int idx = i0 + i;
        size_t r = (size_t)(idx / 12) * H + bid * 12 + (idx % 12);
        waH[i]  = g_WA + r * CAW;            // layer0 hh   (cols 0..1535)
        waX[i]  = g_WA + r * CAW + H / 2;    // layer0 x/emb (cols 1536..1791)
        wbI[i]  = g_WB + r * CBW;            // layer1 ih   (cols 0..1535)
        wbH[i]  = g_WB + r * CBW + H / 2;    // layer1 hh   first half (cols 1536..2303)
        wbH2[i] = g_WB + r * CBW + H / 2 + 384; // layer1 hh second half (cols 2304..3071)
    }

    // activation lanes: warp 0, lanes 0..11 own units j = bid*12 + lane
    const int j = bid * 12 + lane;
    float cA = 0.f, cB = 0.f;
    float baI = 0.f, baF = 0.f, baG = 0.f, baO = 0.f;
    float bbI = 0.f, bbF = 0.f, bbG = 0.f, bbO = 0.f;
    if (wid == 0 && lane < 12) {
        cA = c0in[j]; cB = c0in[H + j];
        baI = bi0[j] + bh0[j];                 baF = bi0[H + j] + bh0[H + j];
        baG = bi0[2 * H + j] + bh0[2 * H + j]; baO = bi0[3 * H + j] + bh0[3 * H + j];
        bbI = bi1[j] + bh1[j];                 bbF = bi1[H + j] + bh1[H + j];
        bbG = bi1[2 * H + j] + bh1[2 * H + j]; bbO = bi1[3 * H + j] + bh1[3 * H + j];
    }

    // prologue: initial state into SMEM; emb = 0; prefetch partials
    for (int i = tid; i < H; i += NTHR) { sxh0[i] = __ldg(h0in + i); sxh1[i] = __ldg(h0in + H + i); }
    for (int i = tid; i < EMB; i += NTHR) semb[i] = 0.f;
    __syncthreads();
    float2 pA[3] = {{0,0},{0,0},{0,0}}, pB[3] = {{0,0},{0,0},{0,0}};
    dotp<3, 6>(waH, sxh0, lane, pA);     // full layer0-hh partial
    dotp<3, 3>(wbH, sxh1, lane, pB);     // layer1-hh first half
    __syncthreads();

    unsigned ep = 0;

    for (int t = 0; t < T_STEPS; ++t) {
        // ---- phase A (block-local): x/emb + prefetched hh partial -> h0n ------------
        const float* xin = inputVecs + (size_t)t * IN_DIM;
        if (tid < 256) {
            float v = 0.f;
            if (tid < IN_DIM)   v = __ldg(xin + tid);
            else if (tid < 246) v = semb[tid - IN_DIM];
            sxx[tid] = v;
        }
        __syncthreads();
        {
            float2 a[3] = { pA[0], pA[1], pA[2] };
            dotp<3, 1>(waX, sxx, lane, a);
            #pragma unroll
            for (int i = 0; i < 3; i++) {
                float s = wred(a[i].x + a[i].y);
                if (lane == 0) sgate[i0 + i] = s;
            }
        }
        __syncthreads();
        if (wid == 0 && lane < 12) {
            float gi = sigmoidf_(sgate[lane] + baI);
            float gf = sigmoidf_(sgate[12 + lane] + baF);
            float gg = tanhf    (sgate[24 + lane] + baG);
            float go = sigmoidf_(sgate[36 + lane] + baO);
            cA = gf * cA + gi * gg;
            g_h0v[j] = go * tanhf(cA);
        }
        ep += NBLK; bar_arrive();                                 // bar1: h0n
        // overlap: layer1-hh second-half prefetch (sxh1 still = h1n(t-1))
        dotp<3, 3>(wbH2, sxh1 + 768, lane, pB);
        bar_wait(ep);

        // ---- slot B: critical ih1 dot -> h1n; overlap: layer0-hh prefetch -----------
        if (tid < 384)
            reinterpret_cast<float4*>(sxh0)[tid] =
                __ldcg(reinterpret_cast<const float4*>(g_h0v) + tid);
        __syncthreads();
        {
            float2 a[3] = { pB[0], pB[1], pB[2] };
            dotp<3, 6>(wbI, sxh0, lane, a);
            #pragma unroll
            for (int i = 0; i < 3; i++) {
                float s = wred(a[i].x + a[i].y);
                if (lane == 0) sgate[i0 + i] = s;
            }
        }
        __syncthreads();
        if (wid == 0 && lane < 12) {
            float gi = sigmoidf_(sgate[lane] + bbI);
            float gf = sigmoidf_(sgate[12 + lane] + bbF);
            float gg = tanhf    (sgate[24 + lane] + bbG);
            float go = sigmoidf_(sgate[36 + lane] + bbO);
            cB = gf * cB + gi * gg;
            g_h1v[j] = go * tanhf(cB);
        }
        ep += NBLK; bar_arrive();                                 // bar2: h1n
        pA[0] = make_float2(0.f, 0.f); pA[1] = make_float2(0.f, 0.f); pA[2] = make_float2(0.f, 0.f);
        dotp<3, 6>(waH, sxh0, lane, pA);   // layer0-hh prefetch for t+1
        bar_wait(ep);

        // ---- slot E: critical logit; overlap: layer1-hh first-half prefetch ---------
        if (tid < 384)
            reinterpret_cast<float4*>(sxh1)[tid] =
                __ldcg(reinterpret_cast<const float4*>(g_h1v) + tid);
        __syncthreads();
        if (wid < 12) {
            int c = wid * 128 + lane * 4;
            float4 x = *reinterpret_cast<const float4*>(sxh1 + c);
            float4 w = __ldg(reinterpret_cast<const float4*>(g_WCB + (size_t)bid * H + c));
            float a = x.x * w.x + x.y * w.y + x.z * w.z + x.w * w.w;
            a = wred(a);
            if (lane == 0) sgate[wid] = a;
        }
        __syncthreads();
        if (tid == 0) {
            float s = 0.f;
            #pragma unroll
            for (int i = 0; i < 12; i++) s += sgate[i];
            g_logits[bid] = s + g_bcomb[bid];
        }
        ep += NBLK; bar_arrive();                                 // bar3: logits
        pB[0] = make_float2(0.f, 0.f); pB[1] = make_float2(0.f, 0.f); pB[2] = make_float2(0.f, 0.f);
        dotp<3, 3>(wbH, sxh1, lane, pB);   // layer1-hh first-half prefetch for t+1
        bar_wait(ep);

        // ---- slot4 (block-local): softmax + emb -------------------------------------
        if (tid < OUTD) sy[tid] = __ldcg(&g_logits[tid]);
        __syncthreads();
        if (wid == 0) {
            float v0 = sy[lane], v1 = sy[lane + 32], v2 = sy[lane + 64], v3 = sy[lane + 96];
            float m = fmaxf(fmaxf(v0, v1), fmaxf(v2, v3));
            #pragma unroll
            for (int o = 16; o; o >>= 1) m = fmaxf(m, __shfl_xor_sync(0xffffffffu, m, o));
            float e0 = expf(v0 - m), e1 = expf(v1 - m), e2 = expf(v2 - m), e3 = expf(v3 - m);
            float s = wred(e0 + e1 + e2 + e3);
            float inv = 1.f / s;
            e0 *= inv; e1 *= inv; e2 *= inv; e3 *= inv;
            sy[lane] = e0; sy[lane + 32] = e1; sy[lane + 64] = e2; sy[lane + 96] = e3;
            if (bid == 0) {
                float* op = out + (size_t)t * OUTD;
                op[lane] = e0; op[lane + 32] = e1; op[lane + 64] = e2; op[lane + 96] = e3;
            }
        }
        __syncthreads();
        for (int r = wid; r < EMB; r += 16) {
            float4 w = __ldg(reinterpret_cast<const float4*>(Wmap + r * OUTD + lane * 4));
            float a = w.x * sy[lane * 4] + w.y * sy[lane * 4 + 1] +
                      w.z * sy[lane * 4 + 2] + w.w * sy[lane * 4 + 3];
            a = wred(a);
            if (lane == 0) semb[r] = a + bm[r];
        }
        __syncthreads();   // semb visible to phase A of t+1
    }

    // end-of-launch reset of barrier counters (last arriver), for graph replay
    if (tid == 0) {
        __threadfence();
        if (atomicAdd(&g_done, 1u) == NBLK - 1) {
            g_count = 0u;
            g_done = 0u;
            __threadfence();
        }
    }
}

// ---------------- launch --------------------------------------------------------------
extern "C" void kernel_launch(void* const* d_in, const int* in_sizes, int n_in,
                              void* d_out, int out_size) {
    const float* inputVecs = (const float*)d_in[0];
    const float* h0    = (const float*)d_in[1];
    const float* c0    = (const float*)d_in[2];
    const float* W_ih0 = (const float*)d_in[3];
    const float* W_hh0 = (const float*)d_in[4];
    const float* b_ih0 = (const float*)d_in[5];
    const float* b_hh0 = (const float*)d_in[6];
    const float* W_ih1 = (const float*)d_in[7];
    const float* W_hh1 = (const float*)d_in[8];
    const float* b_ih1 = (const float*)d_in[9];
    const float* b_hh1 = (const float*)d_in[10];
    const float* W_hl  = (const float*)d_in[11];
    const float* b_hl  = (const float*)d_in[12];
    const float* W_out = (const float*)d_in[13];
    const float* b_out = (const float*)d_in[14];
    const float* W_map = (const float*)d_in[15];
    const float* b_map = (const float*)d_in[16];

    pack_all<<<2048, 256>>>(W_ih0, W_hh0, W_ih1, W_hh1, W_hl, W_out, b_hl, b_out);
    lstm_main<<<NBLK, NTHR>>>(inputVecs, h0, c0,
                              b_ih0, b_hh0, b_ih1, b_hh1,
                              W_map, b_map, (float*)d_out);
}

// round 5
// speedup vs baseline: 2.1970x; 1.0677x over previous
#include <cuda_runtime.h>
#include <cuda_bf16.h>

#define T_STEPS 2048
#define IN_DIM  118
#define EMB     128
#define H       1536
#define H4      6144
#define H2      1024
#define OUTD    128
#define CA      1792   // layer-0 row cols: hh(1536) | x(118) emb(128) | pad(10)
#define CB      3072   // layer-1 row cols: ih(1536) | hh(1536)
#define CAW     (CA/2)
#define CBW     (CB/2)
#define NBLK    128
#define NTHR    1024   // 16 critical warps + 16 prefetch warps

// ---------------- device-global scratch ----------------------------------------------
__device__ __align__(128) unsigned g_WA[(size_t)H4 * CAW];   // ~21 MB (bf16 pairs)
__device__ __align__(128) unsigned g_WB[(size_t)H4 * CBW];   // ~37.7 MB
__device__ __align__(128) float g_WCBT[(size_t)H * OUTD];    // W_comb^T (c-major)
__device__ __align__(128) unsigned g_WMp[EMB * OUTD / 2];    // W_map bf16 pairs
__device__ float g_bcomb[OUTD];
__device__ __align__(16) float g_h0v[H];
__device__ __align__(16) float g_h1v[H];
__device__ float g_L[2][OUTD];       // double-buffered logit accumulators
__device__ unsigned g_count = 0;
__device__ unsigned g_done  = 0;

// ---------------- bf16-pair packing with hi-compensation ------------------------------
__device__ __forceinline__ unsigned pack2(float wlo, float whi) {
    unsigned lo16 = (unsigned)__bfloat16_as_ushort(__float2bfloat16(wlo));
    unsigned base = __float_as_uint(whi) & 0xffff0000u;
    unsigned c0 = base | lo16, c1 = (base + 0x10000u) | lo16, c2 = (base - 0x10000u) | lo16;
    float d0 = fabsf(__uint_as_float(c0) - whi);
    float d1 = fabsf(__uint_as_float(c1) - whi);
    float d2 = fabsf(__uint_as_float(c2) - whi);
    unsigned best = c0; float bd = d0;
    if (d1 < bd) { bd = d1; best = c1; }
    if (d2 < bd) { best = c2; }
    return best;
}

__device__ __forceinline__ float srcA(const float* Wih0, const float* Whh0, size_t r, int c) {
    if (c < H)       return Whh0[r * H + c];
    if (c < H + 246) return Wih0[r * 246 + (c - H)];
    return 0.f;
}

// Single pack kernel: WA, WB, WCBT (transposed comb), WMp, bcomb.
__global__ void pack_all(const float* __restrict__ Wih0, const float* __restrict__ Whh0,
                         const float* __restrict__ Wih1, const float* __restrict__ Whh1,
                         const float* __restrict__ Whl,  const float* __restrict__ Wout,
                         const float* __restrict__ bhl,  const float* __restrict__ bout,
                         const float* __restrict__ Wmap) {
    const size_t nA = (size_t)H4 * CAW;
    const size_t nB = (size_t)H4 * CBW;
    const size_t nCT = (size_t)H * OUTD;
    const size_t nM = (size_t)EMB * OUTD / 2;
    const size_t total = nA + nB + nCT + nM + OUTD;
    size_t stride = (size_t)gridDim.x * blockDim.x;
    for (size_t i = (size_t)blockIdx.x * blockDim.x + threadIdx.x; i < total; i += stride) {
        if (i < nA) {
            size_t r = i / CAW;
            int c = 2 * (int)(i % CAW);
            g_WA[i] = pack2(srcA(Wih0, Whh0, r, c), srcA(Wih0, Whh0, r, c + 1));
        } else if (i < nA + nB) {
            size_t k = i - nA;
            size_t r = k / CBW;
            int c = 2 * (int)(k % CBW);
            float lo = (c < H)     ? Wih1[r * H + c]     : Whh1[r * H + (c - H)];
            float hi = (c + 1 < H) ? Wih1[r * H + c + 1] : Whh1[r * H + (c + 1 - H)];
            g_WB[k] = pack2(lo, hi);
        } else if (i < nA + nB + nCT) {
            size_t k = i - nA - nB;
            int c = (int)(k / OUTD), r = (int)(k % OUTD);
            float s = 0.f;
            #pragma unroll 4
            for (int kk = 0; kk < H2; kk++)
                s = fmaf(__ldg(Wout + r * H2 + kk), __ldg(Whl + (size_t)kk * H + c), s);
            g_WCBT[k] = s;
        } else if (i < nA + nB + nCT + nM) {
            size_t k = i - nA - nB - nCT;
            int r = (int)(k / (OUTD / 2)), q = (int)(k % (OUTD / 2));
            g_WMp[k] = pack2(Wmap[r * OUTD + 2 * q], Wmap[r * OUTD + 2 * q + 1]);
        } else {
            int r = (int)(i - nA - nB - nCT - nM);
            float s = 0.f;
            #pragma unroll 4
            for (int kk = 0; kk < H2; kk++) s = fmaf(Wout[r * H2 + kk], bhl[kk], s);
            g_bcomb[r] = s + bout[r];
        }
    }
}

// ---------------- core math -----------------------------------------------------------
__device__ __forceinline__ float wred(float a) {
    a += __shfl_xor_sync(0xffffffffu, a, 16);
    a += __shfl_xor_sync(0xffffffffu, a, 8);
    a += __shfl_xor_sync(0xffffffffu, a, 4);
    a += __shfl_xor_sync(0xffffffffu, a, 2);
    a += __shfl_xor_sync(0xffffffffu, a, 1);
    return a;
}

__device__ __forceinline__ float sigmoidf_(float x) { return 1.f / (1.f + expf(-x)); }

// packed bf16-pair FMA: acc(pair) += decode(w) * (x0,x1)   [1 SHL + 1 FFMA2]
__device__ __forceinline__ void bffma2(float& a0, float& a1, unsigned w, float x0, float x1) {
    asm("{\n\t"
        ".reg .b32 lo;\n\t"
        ".reg .b64 wp, xp, ap;\n\t"
        "shl.b32 lo, %2, 16;\n\t"
        "mov.b64 wp, {lo, %2};\n\t"
        "mov.b64 xp, {%3, %4};\n\t"
        "mov.b64 ap, {%0, %1};\n\t"
        "fma.rn.f32x2 ap, wp, xp, ap;\n\t"
        "mov.b64 {%0, %1}, ap;\n\t"
        "}" : "+f"(a0), "+f"(a1) : "r"(w), "f"(x0), "f"(x1));
}

// 3-row dot over NIT*256 cols; weight stream via .cg (keep L1 for reused tensors).
template <int NIT>
__device__ __forceinline__ void dot3(const unsigned* __restrict__ w0,
                                     const unsigned* __restrict__ w1,
                                     const unsigned* __restrict__ w2,
                                     const float* __restrict__ sx, int lane,
                                     float2& A0, float2& A1, float2& A2) {
    #pragma unroll 2
    for (int it = 0; it < NIT; ++it) {
        const int kf = it * 256 + lane * 8;
        const int kw = it * 128 + lane * 4;
        float4 x0 = *reinterpret_cast<const float4*>(sx + kf);
        float4 x1 = *reinterpret_cast<const float4*>(sx + kf + 4);
        uint4 v0 = __ldcg(reinterpret_cast<const uint4*>(w0 + kw));
        uint4 v1 = __ldcg(reinterpret_cast<const uint4*>(w1 + kw));
        uint4 v2 = __ldcg(reinterpret_cast<const uint4*>(w2 + kw));
        bffma2(A0.x, A0.y, v0.x, x0.x, x0.y); bffma2(A0.x, A0.y, v0.y, x0.z, x0.w);
        bffma2(A0.x, A0.y, v0.z, x1.x, x1.y); bffma2(A0.x, A0.y, v0.w, x1.z, x1.w);
        bffma2(A1.x, A1.y, v1.x, x0.x, x0.y); bffma2(A1.x, A1.y, v1.y, x0.z, x0.w);
        bffma2(A1.x, A1.y, v1.z, x1.x, x1.y); bffma2(A1.x, A1.y, v1.w, x1.z, x1.w);
        bffma2(A2.x, A2.y, v2.x, x0.x, x0.y); bffma2(A2.x, A2.y, v2.y, x0.z, x0.w);
        bffma2(A2.x, A2.y, v2.z, x1.x, x1.y); bffma2(A2.x, A2.y, v2.w, x1.z, x1.w);
    }
}

#define BARC() asm volatile("bar.sync 1, 512;" ::: "memory")
#define BARP() asm volatile("bar.sync 2, 512;" ::: "memory")

__device__ __forceinline__ void bar_arrive_leader() {
    asm volatile("red.release.gpu.global.add.u32 [%0], 1;" :: "l"(&g_count) : "memory");
}
__device__ __forceinline__ void bar_poll_leader(unsigned target) {
    unsigned v;
    do {
        asm volatile("ld.acquire.gpu.global.u32 %0, [%1];" : "=r"(v) : "l"(&g_count) : "memory");
    } while (v < target);
}

// ---------------- persistent main kernel ----------------------------------------------
__global__ void __launch_bounds__(NTHR, 1) lstm_main(
    const float* __restrict__ inputVecs,
    const float* __restrict__ h0in, const float* __restrict__ c0in,
    const float* __restrict__ bi0, const float* __restrict__ bh0,
    const float* __restrict__ bi1, const float* __restrict__ bh1,
    const float* __restrict__ bm,
    float* __restrict__ out) {
    __shared__ __align__(16) float sxh0[H];     // C gather of h0n
    __shared__ __align__(16) float spxh0[H];    // P gather of h0n
    __shared__ __align__(16) float spxh1[H];    // P gather of h1n
    __shared__ __align__(16) float sxx[256];
    __shared__ float sgate[48], sh1[12];
    __shared__ float pArow[48], pBrow[48];      // P -> C handoff (wred'ed hh partials)
    __shared__ float sy[OUTD], semb[EMB], sbm[EMB];

    const int tid = threadIdx.x, lane = tid & 31, bid = blockIdx.x;

    unsigned ep1 = NBLK, ep2 = 2 * NBLK;

    if (tid < 512) {
        // =========================== C-group (critical path) =========================
        const int wid = tid >> 5;
        const int i0 = wid * 3;
        const unsigned *waX[3], *wbI[3];
        #pragma unroll
        for (int i = 0; i < 3; i++) {
            int idx = i0 + i;
            size_t r = (size_t)(idx / 12) * H + bid * 12 + (idx % 12);
            waX[i] = g_WA + r * CAW + H / 2;   // layer0 x/emb (cols 1536..1791)
            wbI[i] = g_WB + r * CBW;           // layer1 ih    (cols 0..1535)
        }
        const int j = bid * 12 + lane;
        float cA = 0.f, cB = 0.f;
        float baI = 0.f, baF = 0.f, baG = 0.f, baO = 0.f;
        float bbI = 0.f, bbF = 0.f, bbG = 0.f, bbO = 0.f;
        if (wid == 0 && lane < 12) {
            cA = c0in[j]; cB = c0in[H + j];
            baI = bi0[j] + bh0[j];                 baF = bi0[H + j] + bh0[H + j];
            baG = bi0[2 * H + j] + bh0[2 * H + j]; baO = bi0[3 * H + j] + bh0[3 * H + j];
            bbI = bi1[j] + bh1[j];                 bbF = bi1[H + j] + bh1[H + j];
            bbG = bi1[2 * H + j] + bh1[2 * H + j]; bbO = bi1[3 * H + j] + bh1[3 * H + j];
        }
        for (int i = tid; i < EMB; i += 512) { semb[i] = 0.f; sbm[i] = __ldg(bm + i); }
        if (tid == 0) {
            float bc = __ldg(&g_bcomb[bid]);
            g_L[0][bid] = bc; g_L[1][bid] = bc;
        }

        for (int t = 0; t < T_STEPS; ++t) {
            __syncthreads();   // step boundary: P handoff (pArow/pBrow) + semb visible
            // ---- phase A (block-local): x/emb dot + pArow -> h0n --------------------
            const float* xin = inputVecs + (size_t)t * IN_DIM;
            if (tid < 256) {
                float v = 0.f;
                if (tid < IN_DIM)   v = __ldg(xin + tid);
                else if (tid < 246) v = semb[tid - IN_DIM];
                sxx[tid] = v;
            }
            BARC();
            {
                float2 a0 = {0, 0}, a1 = {0, 0}, a2 = {0, 0};
                dot3<1>(waX[0], waX[1], waX[2], sxx, lane, a0, a1, a2);
                float s0 = wred(a0.x + a0.y), s1 = wred(a1.x + a1.y), s2 = wred(a2.x + a2.y);
                if (lane == 0) {
                    sgate[i0]     = s0 + pArow[i0];
                    sgate[i0 + 1] = s1 + pArow[i0 + 1];
                    sgate[i0 + 2] = s2 + pArow[i0 + 2];
                }
            }
            BARC();
            if (wid == 0 && lane < 12) {
                float gi = sigmoidf_(sgate[lane] + baI);
                float gf = sigmoidf_(sgate[12 + lane] + baF);
                float gg = tanhf    (sgate[24 + lane] + baG);
                float go = sigmoidf_(sgate[36 + lane] + baO);
                cA = gf * cA + gi * gg;
                g_h0v[j] = go * tanhf(cA);
            }
            BARC();
            if (tid == 0) { bar_arrive_leader(); bar_poll_leader(ep1); }   // bar1
            BARC();
            // ---- slot B: gather h0n, ih1 dot + pBrow -> h1n, local rank-update ------
            if (tid < 384)
                reinterpret_cast<float4*>(sxh0)[tid] =
                    __ldcg(reinterpret_cast<const float4*>(g_h0v) + tid);
            BARC();
            {
                float2 a0 = {0, 0}, a1 = {0, 0}, a2 = {0, 0};
                dot3<6>(wbI[0], wbI[1], wbI[2], sxh0, lane, a0, a1, a2);
                float s0 = wred(a0.x + a0.y), s1 = wred(a1.x + a1.y), s2 = wred(a2.x + a2.y);
                if (lane == 0) {
                    sgate[i0]     = s0 + pBrow[i0];
                    sgate[i0 + 1] = s1 + pBrow[i0 + 1];
                    sgate[i0 + 2] = s2 + pBrow[i0 + 2];
                }
            }
            BARC();
            if (wid == 0 && lane < 12) {
                float gi = sigmoidf_(sgate[lane] + bbI);
                float gf = sigmoidf_(sgate[12 + lane] + bbF);
                float gg = tanhf    (sgate[24 + lane] + bbG);
                float go = sigmoidf_(sgate[36 + lane] + bbO);
                cB = gf * cB + gi * gg;
                float h1n = go * tanhf(cB);
                g_h1v[j] = h1n;
                sh1[lane] = h1n;
            }
            BARC();
            if (tid < OUTD) {   // rank-12 logit update (local h1n x WcbT rows)
                float p = 0.f;
                const float* wc = g_WCBT + (size_t)(bid * 12) * OUTD + tid;
                #pragma unroll
                for (int i = 0; i < 12; i++)
                    p = fmaf(__ldg(wc + i * OUTD), sh1[i], p);
                asm volatile("red.relaxed.gpu.global.add.f32 [%0], %1;"
                             :: "l"(&g_L[t & 1][tid]), "f"(p) : "memory");
            }
            BARC();
            if (tid == 0) { bar_arrive_leader(); bar_poll_leader(ep2); }   // bar2
            BARC();
            // ---- slot4 (block-local): softmax + emb ---------------------------------
            if (tid < OUTD) sy[tid] = __ldcg(&g_L[t & 1][tid]);
            BARC();
            if (wid == 0) {
                float v0 = sy[lane], v1 = sy[lane + 32], v2 = sy[lane + 64], v3 = sy[lane + 96];
                float m = fmaxf(fmaxf(v0, v1), fmaxf(v2, v3));
                #pragma unroll
                for (int o = 16; o; o >>= 1) m = fmaxf(m, __shfl_xor_sync(0xffffffffu, m, o));
                float e0 = expf(v0 - m), e1 = expf(v1 - m), e2 = expf(v2 - m), e3 = expf(v3 - m);
                float s = wred(e0 + e1 + e2 + e3);
                float inv = 1.f / s;
                e0 *= inv; e1 *= inv; e2 *= inv; e3 *= inv;
                sy[lane] = e0; sy[lane + 32] = e1; sy[lane + 64] = e2; sy[lane + 96] = e3;
                if (bid == 0) {
                    float* op = out + (size_t)t * OUTD;
                    op[lane] = e0; op[lane + 32] = e1; op[lane + 64] = e2; op[lane + 96] = e3;
                }
            }
            if (tid == 32)   // reset other buffer for step t+1 (safe: proven by barrier chain)
                g_L[(t + 1) & 1][bid] = __ldg(&g_bcomb[bid]);
            BARC();
            {   // emb: 8 rows per warp from L1-resident bf16-pair W_map
                float xa = sy[lane * 4], xb = sy[lane * 4 + 1];
                float xc = sy[lane * 4 + 2], xd = sy[lane * 4 + 3];
                #pragma unroll
                for (int q = 0; q < 8; q++) {
                    int r = wid * 8 + q;
                    const unsigned* wm = g_WMp + r * (OUTD / 2) + lane * 2;
                    float a0 = 0.f, a1 = 0.f;
                    bffma2(a0, a1, __ldg(wm), xa, xb);
                    bffma2(a0, a1, __ldg(wm + 1), xc, xd);
                    float s = wred(a0 + a1);
                    if (lane == 0) semb[r] = s + sbm[r];
                }
            }
            ep1 += 2 * NBLK; ep2 += 2 * NBLK;
        }
    } else {
        // =========================== P-group (hh prefetch) ===========================
        const int ptid = tid - 512;
        const int pwid = ptid >> 5;
        const int i0 = pwid * 3;
        const unsigned *waH[3], *wbH[3];
        #pragma unroll
        for (int i = 0; i < 3; i++) {
            int idx = i0 + i;
            size_t r = (size_t)(idx / 12) * H + bid * 12 + (idx % 12);
            waH[i] = g_WA + r * CAW;           // layer0 hh (cols 0..1535)
            wbH[i] = g_WB + r * CBW + H / 2;   // layer1 hh (cols 1536..3071)
        }
        // prologue: partials from initial state
        for (int i = ptid; i < H; i += 512) { spxh0[i] = __ldg(h0in + i); spxh1[i] = __ldg(h0in + H + i); }
        BARP();
        {
            float2 a0 = {0,0}, a1 = {0,0}, a2 = {0,0};
            dot3<6>(waH[0], waH[1], waH[2], spxh0, lane, a0, a1, a2);
            float s0 = wred(a0.x + a0.y), s1 = wred(a1.x + a1.y), s2 = wred(a2.x + a2.y);
            if (lane == 0) { pArow[i0] = s0; pArow[i0 + 1] = s1; pArow[i0 + 2] = s2; }
        }
        {
            float2 a0 = {0,0}, a1 = {0,0}, a2 = {0,0};
            dot3<6>(wbH[0], wbH[1], wbH[2], spxh1, lane, a0, a1, a2);
            float s0 = wred(a0.x + a0.y), s1 = wred(a1.x + a1.y), s2 = wred(a2.x + a2.y);
            if (lane == 0) { pBrow[i0] = s0; pBrow[i0 + 1] = s1; pBrow[i0 + 2] = s2; }
        }

        for (int t = 0; t < T_STEPS; ++t) {
            __syncthreads();   // step boundary (shared with C)
            // wait bar1 (h0n ready) -> prefetch pA = waH . h0n(t) for phase A(t+1)
            if (ptid == 0) bar_poll_leader(ep1);
            BARP();
            if (ptid < 384)
                reinterpret_cast<float4*>(spxh0)[ptid] =
                    __ldcg(reinterpret_cast<const float4*>(g_h0v) + ptid);
            BARP();
            {
                float2 a0 = {0,0}, a1 = {0,0}, a2 = {0,0};
                dot3<6>(waH[0], waH[1], waH[2], spxh0, lane, a0, a1, a2);
                float s0 = wred(a0.x + a0.y), s1 = wred(a1.x + a1.y), s2 = wred(a2.x + a2.y);
                if (lane == 0) { pArow[i0] = s0; pArow[i0 + 1] = s1; pArow[i0 + 2] = s2; }
            }
            // wait bar2 (h1n ready) -> prefetch pB = wbH . h1n(t) for slot B(t+1)
            if (ptid == 0) bar_poll_leader(ep2);
            BARP();
            if (ptid < 384)
                reinterpret_cast<float4*>(spxh1)[ptid] =
                    __ldcg(reinterpret_cast<const float4*>(g_h1v) + ptid);
            BARP();
            {
                float2 a0 = {0,0}, a1 = {0,0}, a2 = {0,0};
                dot3<6>(wbH[0], wbH[1], wbH[2], spxh1, lane, a0, a1, a2);
                float s0 = wred(a0.x + a0.y), s1 = wred(a1.x + a1.y), s2 = wred(a2.x + a2.y);
                if (lane == 0) { pBrow[i0] = s0; pBrow[i0 + 1] = s1; pBrow[i0 + 2] = s2; }
            }
            ep1 += 2 * NBLK; ep2 += 2 * NBLK;
        }
    }

    // end-of-launch reset of barrier counters (last arriver), for graph replay
    __syncthreads();
    if (tid == 0) {
        __threadfence();
        if (atomicAdd(&g_done, 1u) == NBLK - 1) {
            g_count = 0u;
            g_done = 0u;
            __threadfence();
        }
    }
}

// ---------------- launch --------------------------------------------------------------
extern "C" void kernel_launch(void* const* d_in, const int* in_sizes, int n_in,
                              void* d_out, int out_size) {
    const float* inputVecs = (const float*)d_in[0];
    const float* h0    = (const float*)d_in[1];
    const float* c0    = (const float*)d_in[2];
    const float* W_ih0 = (const float*)d_in[3];
    const float* W_hh0 = (const float*)d_in[4];
    const float* b_ih0 = (const float*)d_in[5];
    const float* b_hh0 = (const float*)d_in[6];
    const float* W_ih1 = (const float*)d_in[7];
    const float* W_hh1 = (const float*)d_in[8];
    const float* b_ih1 = (const float*)d_in[9];
    const float* b_hh1 = (const float*)d_in[10];
    const float* W_hl  = (const float*)d_in[11];
    const float* b_hl  = (const float*)d_in[12];
    const float* W_out = (const float*)d_in[13];
    const float* b_out = (const float*)d_in[14];
    const float* W_map = (const float*)d_in[15];
    const float* b_map = (const float*)d_in[16];

    pack_all<<<2048, 256>>>(W_ih0, W_hh0, W_ih1, W_hh1, W_hl, W_out, b_hl, b_out, W_map);
    lstm_main<<<NBLK, NTHR>>>(inputVecs, h0, c0,
                              b_ih0, b_hh0, b_ih1, b_hh1,
                              b_map, (float*)d_out);
}